// round 12
// baseline (speedup 1.0000x reference)
#include <cuda_runtime.h>
#include <cuda_bf16.h>

#define NBLK 888    // 148 SMs * 6 resident blocks -> one exact wave
#define NTHR 256

__device__ float g_partial[NBLK];
__device__ unsigned int g_count = 0;

typedef unsigned long long u64;

__device__ __forceinline__ float fast_lg2(float x) {
    float r; asm("lg2.approx.f32 %0, %1;" : "=f"(r) : "f"(x)); return r;
}
__device__ __forceinline__ float fast_sqrt(float x) {
    float r; asm("sqrt.approx.f32 %0, %1;" : "=f"(r) : "f"(x)); return r;
}

// ---- packed f32x2 helpers (sm_103) ----
__device__ __forceinline__ u64 pk2(float a, float b) {
    u64 r; asm("mov.b64 %0, {%1, %2};" : "=l"(r) : "f"(a), "f"(b)); return r;
}
__device__ __forceinline__ void upk2(float& a, float& b, u64 v) {
    asm("mov.b64 {%0, %1}, %2;" : "=f"(a), "=f"(b) : "l"(v));
}
__device__ __forceinline__ u64 f2fma(u64 a, u64 b, u64 c) {
    u64 r; asm("fma.rn.f32x2 %0, %1, %2, %3;" : "=l"(r) : "l"(a), "l"(b), "l"(c)); return r;
}
__device__ __forceinline__ u64 f2mul(u64 a, u64 b) {
    u64 r; asm("mul.rn.f32x2 %0, %1, %2;" : "=l"(r) : "l"(a), "l"(b)); return r;
}
__device__ __forceinline__ u64 f2add(u64 a, u64 b) {
    u64 r; asm("add.rn.f32x2 %0, %1, %2;" : "=l"(r) : "l"(a), "l"(b)); return r;
}
__device__ __forceinline__ u64 bc(float x) { return pk2(x, x); }

// Two elements, packed math, 3 MUFU/elem (2 lg2 + sqrt).
// loss(unclamped) = 0.9*w*(w+2) = 0.9*(u^2 - 1), u = w+1 = rho*h(rho).
// loss(clamped)   = lmt*e + 0.9, selected on lmt.
__device__ __forceinline__ void superloss_pair(float p0, float p1, float t0, float t1,
                                               u64& d_acc) {
    const float CLAMP_LMT = -0.66218299410859620f;  // 1.8 * (-1/e)

    const u64 C_M1    = bc(-1.0f);
    const u64 C_LN2   = bc(0.69314718055994531f);
    const u64 C_MLN2  = bc(-0.69314718055994531f);
    const u64 C_M15   = bc(-1.5f);
    const u64 C_R2C   = bc(3.02031314273227248f);   // 2e/1.8
    const u64 C_2     = bc(2.0f);
    const u64 C_09    = bc(0.9f);
    const u64 C_M09   = bc(-0.9f);
    const u64 C_E     = bc(2.71828182845904523f);
    const u64 C_P6 = bc(2.72851e-5f);
    const u64 C_P5 = bc(-6.43946e-4f);
    const u64 C_P4 = bc(6.307194e-3f);
    const u64 C_P3 = bc(-3.4116882e-2f);
    const u64 C_P2 = bc(0.118663595f);
    const u64 C_P1 = bc(-0.322237288f);
    const u64 C_P0 = bc(1.0f);

    float a0 = fast_lg2(p0),        a1 = fast_lg2(p1);
    float b0 = fast_lg2(1.0f - p0), b1 = fast_lg2(1.0f - p1);

    u64 d_lp  = pk2(a0, a1);
    u64 d_l1p = pk2(b0, b1);
    u64 d_t   = pk2(t0, t1);

    // lmt = l - tau
    u64 d_diff = f2fma(d_lp, C_M1, d_l1p);
    u64 d_tl   = f2mul(d_t, C_LN2);
    u64 d_cc   = f2fma(d_l1p, C_MLN2, C_M15);
    u64 d_lmt  = f2fma(d_tl, d_diff, d_cc);

    // rho^2 = lmt*(2e/1.8) + 2 ; clamp at 0 -> u = 0, loss_u = -0.9 (discarded)
    u64 d_r2 = f2fma(d_lmt, C_R2C, C_2);
    float r20, r21; upk2(r20, r21, d_r2);
    float s0 = fast_sqrt(fmaxf(r20, 0.0f));
    float s1 = fast_sqrt(fmaxf(r21, 0.0f));
    u64 d_rho = pk2(s0, s1);

    // degree-6 init: u = rho*h(rho) = W+1
    u64 h = f2fma(C_P6, d_rho, C_P5);
    h = f2fma(h, d_rho, C_P4);
    h = f2fma(h, d_rho, C_P3);
    h = f2fma(h, d_rho, C_P2);
    h = f2fma(h, d_rho, C_P1);
    h = f2fma(h, d_rho, C_P0);
    u64 d_u = f2mul(d_rho, h);

    // loss_u = 0.9*(u^2 - 1) = (0.9u)*u - 0.9 ; loss_c = lmt*e + 0.9
    u64 d_u9 = f2mul(d_u, C_09);
    u64 d_lu = f2fma(d_u9, d_u, C_M09);
    u64 d_lc = f2fma(d_lmt, C_E, C_09);

    float lu0, lu1; upk2(lu0, lu1, d_lu);
    float lc0, lc1; upk2(lc0, lc1, d_lc);
    float lm0, lm1; upk2(lm0, lm1, d_lmt);
    float r0 = (lm0 < CLAMP_LMT) ? lc0 : lu0;
    float r1 = (lm1 < CLAMP_LMT) ? lc1 : lu1;
    d_acc = f2add(d_acc, pk2(r0, r1));
}

__device__ __forceinline__ float superloss_scalar(float p, float t) {
    const float LN2 = 0.69314718055994531f;
    const float E   = 2.71828182845904523f;
    const float CLAMP_LMT = -0.66218299410859620f;

    float lp2  = fast_lg2(p);
    float l1p2 = fast_lg2(1.0f - p);
    float nl2 = fmaf(t, l1p2 - lp2, -l1p2);
    float lmt = fmaf(LN2, nl2, -1.5f);
    float r2 = fmaf(lmt, 3.02031314273227f, 2.0f);
    float rho = fast_sqrt(fmaxf(r2, 0.0f));
    float h = fmaf(rho, 2.72851e-5f, -6.43946e-4f);
    h = fmaf(h, rho,  6.307194e-3f);
    h = fmaf(h, rho, -3.4116882e-2f);
    h = fmaf(h, rho,  0.118663595f);
    h = fmaf(h, rho, -0.322237288f);
    h = fmaf(h, rho,  1.0f);
    float u = rho * h;
    float lu = fmaf(0.9f * u, u, -0.9f);
    float lc = fmaf(lmt, E, 0.9f);
    return (lmt < CLAMP_LMT) ? lc : lu;
}

__global__ void __launch_bounds__(NTHR, 6)
superloss_fused(const float* __restrict__ logits,
                const float* __restrict__ targets,
                float* __restrict__ out,
                int n) {
    int tid = threadIdx.x;
    int gtid = blockIdx.x * NTHR + tid;
    int nv = n >> 2;
    int stride = NBLK * NTHR;

    const float4* lp4 = reinterpret_cast<const float4*>(logits);
    const float4* tp4 = reinterpret_cast<const float4*>(targets);

    u64 d_acc_a = bc(0.0f);
    u64 d_acc_b = bc(0.0f);

    // Guardless unroll-2: 4 LDG.128 front-batched (MLP=4), two independent
    // chains into separate accumulators.
    int i = gtid;
    for (; i + stride < nv; i += 2 * stride) {
        float4 pa = __ldcs(lp4 + i);
        float4 ta = __ldcs(tp4 + i);
        float4 pb = __ldcs(lp4 + i + stride);
        float4 tb = __ldcs(tp4 + i + stride);
        superloss_pair(pa.x, pa.y, ta.x, ta.y, d_acc_a);
        superloss_pair(pb.x, pb.y, tb.x, tb.y, d_acc_b);
        superloss_pair(pa.z, pa.w, ta.z, ta.w, d_acc_a);
        superloss_pair(pb.z, pb.w, tb.z, tb.w, d_acc_b);
    }
    if (i < nv) {
        float4 pa = __ldcs(lp4 + i);
        float4 ta = __ldcs(tp4 + i);
        superloss_pair(pa.x, pa.y, ta.x, ta.y, d_acc_a);
        superloss_pair(pa.z, pa.w, ta.z, ta.w, d_acc_b);
    }

    u64 d_acc = f2add(d_acc_a, d_acc_b);
    float acc0, acc1; upk2(acc0, acc1, d_acc);
    int tail_start = nv << 2;
    for (int k = tail_start + gtid; k < n; k += stride)
        acc0 += superloss_scalar(logits[k], targets[k]);

    float acc = acc0 + acc1;

    __shared__ float s[NTHR];
    __shared__ bool is_last;
    s[tid] = acc;
    __syncthreads();
#pragma unroll
    for (int o = NTHR / 2; o > 0; o >>= 1) {
        if (tid < o) s[tid] += s[tid + o];
        __syncthreads();
    }
    if (tid == 0) {
        g_partial[blockIdx.x] = s[0];
        __threadfence();
        unsigned int prev = atomicInc(&g_count, NBLK - 1);
        is_last = (prev == NBLK - 1);
    }
    __syncthreads();

    if (is_last) {
        __threadfence();
        volatile float* gp = g_partial;
        float a = 0.0f;
        for (int j = tid; j < NBLK; j += NTHR) a += gp[j];
        s[tid] = a;
        __syncthreads();
#pragma unroll
        for (int o = NTHR / 2; o > 0; o >>= 1) {
            if (tid < o) s[tid] += s[tid + o];
            __syncthreads();
        }
        if (tid == 0) out[0] = s[0] * (1.0f / 32.0f);
    }
}

extern "C" void kernel_launch(void* const* d_in, const int* in_sizes, int n_in,
                              void* d_out, int out_size) {
    const float* logits  = (const float*)d_in[0];
    const float* targets = (const float*)d_in[1];
    float* out = (float*)d_out;
    int n = in_sizes[0];

    superloss_fused<<<NBLK, NTHR>>>(logits, targets, out, n);
}

// round 13
// speedup vs baseline: 1.0169x; 1.0169x over previous
#include <cuda_runtime.h>
#include <cuda_bf16.h>

#define NBLK 1184
#define NTHR 256

__device__ float g_partial[NBLK];
__device__ unsigned int g_count = 0;

typedef unsigned long long u64;

__device__ __forceinline__ float fast_lg2(float x) {
    float r; asm("lg2.approx.f32 %0, %1;" : "=f"(r) : "f"(x)); return r;
}
__device__ __forceinline__ float fast_sqrt(float x) {
    float r; asm("sqrt.approx.f32 %0, %1;" : "=f"(r) : "f"(x)); return r;
}

// ---- packed f32x2 helpers (sm_103) ----
__device__ __forceinline__ u64 pk2(float a, float b) {
    u64 r; asm("mov.b64 %0, {%1, %2};" : "=l"(r) : "f"(a), "f"(b)); return r;
}
__device__ __forceinline__ void upk2(float& a, float& b, u64 v) {
    asm("mov.b64 {%0, %1}, %2;" : "=f"(a), "=f"(b) : "l"(v));
}
__device__ __forceinline__ u64 f2fma(u64 a, u64 b, u64 c) {
    u64 r; asm("fma.rn.f32x2 %0, %1, %2, %3;" : "=l"(r) : "l"(a), "l"(b), "l"(c)); return r;
}
__device__ __forceinline__ u64 f2mul(u64 a, u64 b) {
    u64 r; asm("mul.rn.f32x2 %0, %1, %2;" : "=l"(r) : "l"(a), "l"(b)); return r;
}
__device__ __forceinline__ u64 f2add(u64 a, u64 b) {
    u64 r; asm("add.rn.f32x2 %0, %1, %2;" : "=l"(r) : "l"(a), "l"(b)); return r;
}
__device__ __forceinline__ u64 bc(float x) { return pk2(x, x); }

// Constant-folded form. q = l1p2 + t*(lp2 - l1p2) = -l/ln2.
//   rho^2  = q*K1 + K2          (K1 = -ln2*2e/1.8, K2 = 2 - 1.5*2e/1.8)
//   loss_c = q*K3 + K4          (K3 = -ln2*e,      K4 = 0.9 - 1.5*e)
//   clamp when q > QC           (QC = -(CLAMP+1.5)/ln2... sign-resolved)
// Init poly pre-scaled by sqrt(0.9): u' = sqrt(0.9)*(W+1) = rho*h'(rho),
//   loss_u = u'^2 - 0.9.
__device__ __forceinline__ void superloss_pair(float p0, float p1, float t0, float t1,
                                               u64& d_acc) {
    const float QC = -1.2087143f;                    // clamp when q > QC

    const u64 C_M1  = bc(-1.0f);
    const u64 C_K1  = bc(-2.0935215460f);
    const u64 C_K2  = bc(-2.5304697141f);
    const u64 C_K3  = bc(-1.8841698127f);
    const u64 C_K4  = bc(-3.1774227427f);
    const u64 C_M09 = bc(-0.9f);
    // degree-6 coefficients scaled by sqrt(0.9)=0.9486832981
    const u64 C_P6 = bc(2.588513e-5f);
    const u64 C_P5 = bc(-6.109016e-4f);
    const u64 C_P4 = bc(5.983530e-3f);
    const u64 C_P3 = bc(-3.2366116e-2f);
    const u64 C_P2 = bc(0.112574175f);
    const u64 C_P1 = bc(-0.305701133f);
    const u64 C_P0 = bc(0.9486832981f);

    float a0 = fast_lg2(p0),        a1 = fast_lg2(p1);
    float b0 = fast_lg2(1.0f - p0), b1 = fast_lg2(1.0f - p1);

    u64 d_lp  = pk2(a0, a1);
    u64 d_l1p = pk2(b0, b1);
    u64 d_t   = pk2(t0, t1);

    u64 d_diff = f2fma(d_l1p, C_M1, d_lp);        // lp2 - l1p2
    u64 d_q    = f2fma(d_t, d_diff, d_l1p);       // q
    u64 d_r2   = f2fma(d_q, C_K1, C_K2);          // rho^2 (0 at clamp bound)
    u64 d_lc   = f2fma(d_q, C_K3, C_K4);          // clamped loss

    float r20, r21; upk2(r20, r21, d_r2);
    float s0 = fast_sqrt(fmaxf(r20, 0.0f));
    float s1 = fast_sqrt(fmaxf(r21, 0.0f));
    u64 d_rho = pk2(s0, s1);

    u64 h = f2fma(C_P6, d_rho, C_P5);
    h = f2fma(h, d_rho, C_P4);
    h = f2fma(h, d_rho, C_P3);
    h = f2fma(h, d_rho, C_P2);
    h = f2fma(h, d_rho, C_P1);
    h = f2fma(h, d_rho, C_P0);
    u64 d_u  = f2mul(d_rho, h);                   // u' = sqrt(0.9)*(W+1)
    u64 d_lu = f2fma(d_u, d_u, C_M09);            // loss_u = u'^2 - 0.9

    float lu0, lu1; upk2(lu0, lu1, d_lu);
    float lc0, lc1; upk2(lc0, lc1, d_lc);
    float q0, q1;   upk2(q0, q1, d_q);
    float r0 = (q0 > QC) ? lc0 : lu0;
    float r1 = (q1 > QC) ? lc1 : lu1;
    d_acc = f2add(d_acc, pk2(r0, r1));
}

__device__ __forceinline__ float superloss_scalar(float p, float t) {
    const float QC = -1.2087143f;

    float lp2  = fast_lg2(p);
    float l1p2 = fast_lg2(1.0f - p);
    float q = fmaf(t, lp2 - l1p2, l1p2);
    float r2 = fmaf(q, -2.0935215460f, -2.5304697141f);
    float lc = fmaf(q, -1.8841698127f, -3.1774227427f);
    float rho = fast_sqrt(fmaxf(r2, 0.0f));
    float h = fmaf(rho, 2.588513e-5f, -6.109016e-4f);
    h = fmaf(h, rho,  5.983530e-3f);
    h = fmaf(h, rho, -3.2366116e-2f);
    h = fmaf(h, rho,  0.112574175f);
    h = fmaf(h, rho, -0.305701133f);
    h = fmaf(h, rho,  0.9486832981f);
    float u = rho * h;
    float lu = fmaf(u, u, -0.9f);
    return (q > QC) ? lc : lu;
}

__global__ void __launch_bounds__(NTHR, 8)
superloss_fused(const float* __restrict__ logits,
                const float* __restrict__ targets,
                float* __restrict__ out,
                int n) {
    int tid = threadIdx.x;
    int gtid = blockIdx.x * NTHR + tid;
    int nv = n >> 2;
    int stride = NBLK * NTHR;

    const float4* lp4 = reinterpret_cast<const float4*>(logits);
    const float4* tp4 = reinterpret_cast<const float4*>(targets);

    u64 d_acc = bc(0.0f);
    for (int i = gtid; i < nv; i += stride) {
        float4 p4 = __ldcs(lp4 + i);
        float4 t4 = __ldcs(tp4 + i);
        superloss_pair(p4.x, p4.y, t4.x, t4.y, d_acc);
        superloss_pair(p4.z, p4.w, t4.z, t4.w, d_acc);
    }
    float acc0, acc1; upk2(acc0, acc1, d_acc);
    int tail_start = nv << 2;
    for (int k = tail_start + gtid; k < n; k += stride)
        acc0 += superloss_scalar(logits[k], targets[k]);

    float acc = acc0 + acc1;

    __shared__ float s[NTHR];
    __shared__ bool is_last;
    s[tid] = acc;
    __syncthreads();
#pragma unroll
    for (int o = NTHR / 2; o > 0; o >>= 1) {
        if (tid < o) s[tid] += s[tid + o];
        __syncthreads();
    }
    if (tid == 0) {
        g_partial[blockIdx.x] = s[0];
        __threadfence();
        unsigned int prev = atomicInc(&g_count, NBLK - 1);
        is_last = (prev == NBLK - 1);
    }
    __syncthreads();

    if (is_last) {
        __threadfence();
        volatile float* gp = g_partial;
        float a = 0.0f;
        for (int j = tid; j < NBLK; j += NTHR) a += gp[j];
        s[tid] = a;
        __syncthreads();
#pragma unroll
        for (int o = NTHR / 2; o > 0; o >>= 1) {
            if (tid < o) s[tid] += s[tid + o];
            __syncthreads();
        }
        if (tid == 0) out[0] = s[0] * (1.0f / 32.0f);
    }
}

extern "C" void kernel_launch(void* const* d_in, const int* in_sizes, int n_in,
                              void* d_out, int out_size) {
    const float* logits  = (const float*)d_in[0];
    const float* targets = (const float*)d_in[1];
    float* out = (float*)d_out;
    int n = in_sizes[0];

    superloss_fused<<<NBLK, NTHR>>>(logits, targets, out, n);
}

// round 14
// speedup vs baseline: 1.0250x; 1.0079x over previous
#include <cuda_runtime.h>
#include <cuda_bf16.h>

#define NBLK 888    // 148 SMs * 6 resident blocks
#define NTHR 256

__device__ float g_partial[NBLK];
__device__ unsigned int g_count = 0;

typedef unsigned long long u64;

__device__ __forceinline__ float fast_lg2(float x) {
    float r; asm("lg2.approx.f32 %0, %1;" : "=f"(r) : "f"(x)); return r;
}
__device__ __forceinline__ float fast_sqrt(float x) {
    float r; asm("sqrt.approx.f32 %0, %1;" : "=f"(r) : "f"(x)); return r;
}

// ---- packed f32x2 helpers (sm_103) ----
__device__ __forceinline__ u64 pk2(float a, float b) {
    u64 r; asm("mov.b64 %0, {%1, %2};" : "=l"(r) : "f"(a), "f"(b)); return r;
}
__device__ __forceinline__ void upk2(float& a, float& b, u64 v) {
    asm("mov.b64 {%0, %1}, %2;" : "=f"(a), "=f"(b) : "l"(v));
}
__device__ __forceinline__ u64 f2fma(u64 a, u64 b, u64 c) {
    u64 r; asm("fma.rn.f32x2 %0, %1, %2, %3;" : "=l"(r) : "l"(a), "l"(b), "l"(c)); return r;
}
__device__ __forceinline__ u64 f2mul(u64 a, u64 b) {
    u64 r; asm("mul.rn.f32x2 %0, %1, %2;" : "=l"(r) : "l"(a), "l"(b)); return r;
}
__device__ __forceinline__ u64 f2add(u64 a, u64 b) {
    u64 r; asm("add.rn.f32x2 %0, %1, %2;" : "=l"(r) : "l"(a), "l"(b)); return r;
}
__device__ __forceinline__ u64 bc(float x) { return pk2(x, x); }

// q = l1p2 + t*(lp2 - l1p2) = -l/ln2.
//   rho^2  = q*K1 + K2 ; loss_c = q*K3 + K4
// Select on sign of rho^2 (identical value fed to sqrt -> NaN lanes in the
// unclamped path are exactly the lanes the select discards; no fmax needed).
// Init poly pre-scaled by sqrt(0.9): u' = rho*h'(rho); loss_u = u'^2 - 0.9.
__device__ __forceinline__ void superloss_pair(float p0, float p1, float t0, float t1,
                                               u64& d_acc) {
    const u64 C_M1  = bc(-1.0f);
    const u64 C_K1  = bc(-2.0935215460f);
    const u64 C_K2  = bc(-2.5304697141f);
    const u64 C_K3  = bc(-1.8841698127f);
    const u64 C_K4  = bc(-3.1774227427f);
    const u64 C_M09 = bc(-0.9f);
    const u64 C_P6 = bc(2.588513e-5f);
    const u64 C_P5 = bc(-6.109016e-4f);
    const u64 C_P4 = bc(5.983530e-3f);
    const u64 C_P3 = bc(-3.2366116e-2f);
    const u64 C_P2 = bc(0.112574175f);
    const u64 C_P1 = bc(-0.305701133f);
    const u64 C_P0 = bc(0.9486832981f);

    float a0 = fast_lg2(p0),        a1 = fast_lg2(p1);
    float b0 = fast_lg2(1.0f - p0), b1 = fast_lg2(1.0f - p1);

    u64 d_lp  = pk2(a0, a1);
    u64 d_l1p = pk2(b0, b1);
    u64 d_t   = pk2(t0, t1);

    u64 d_diff = f2fma(d_l1p, C_M1, d_lp);        // lp2 - l1p2
    u64 d_q    = f2fma(d_t, d_diff, d_l1p);       // q
    u64 d_r2   = f2fma(d_q, C_K1, C_K2);          // rho^2 (<0 <=> clamped)
    u64 d_lc   = f2fma(d_q, C_K3, C_K4);          // clamped loss

    float r20, r21; upk2(r20, r21, d_r2);
    float s0 = fast_sqrt(r20);                    // NaN if clamped (discarded)
    float s1 = fast_sqrt(r21);
    u64 d_rho = pk2(s0, s1);

    u64 h = f2fma(C_P6, d_rho, C_P5);
    h = f2fma(h, d_rho, C_P4);
    h = f2fma(h, d_rho, C_P3);
    h = f2fma(h, d_rho, C_P2);
    h = f2fma(h, d_rho, C_P1);
    h = f2fma(h, d_rho, C_P0);
    u64 d_u  = f2mul(d_rho, h);                   // u' = sqrt(0.9)*(W+1)
    u64 d_lu = f2fma(d_u, d_u, C_M09);            // loss_u = u'^2 - 0.9

    float lu0, lu1; upk2(lu0, lu1, d_lu);
    float lc0, lc1; upk2(lc0, lc1, d_lc);
    float r0 = (r20 < 0.0f) ? lc0 : lu0;
    float r1 = (r21 < 0.0f) ? lc1 : lu1;
    d_acc = f2add(d_acc, pk2(r0, r1));
}

__device__ __forceinline__ float superloss_scalar(float p, float t) {
    float lp2  = fast_lg2(p);
    float l1p2 = fast_lg2(1.0f - p);
    float q = fmaf(t, lp2 - l1p2, l1p2);
    float r2 = fmaf(q, -2.0935215460f, -2.5304697141f);
    float lc = fmaf(q, -1.8841698127f, -3.1774227427f);
    float rho = fast_sqrt(r2);
    float h = fmaf(rho, 2.588513e-5f, -6.109016e-4f);
    h = fmaf(h, rho,  5.983530e-3f);
    h = fmaf(h, rho, -3.2366116e-2f);
    h = fmaf(h, rho,  0.112574175f);
    h = fmaf(h, rho, -0.305701133f);
    h = fmaf(h, rho,  0.9486832981f);
    float u = rho * h;
    float lu = fmaf(u, u, -0.9f);
    return (r2 < 0.0f) ? lc : lu;
}

__global__ void __launch_bounds__(NTHR, 6)
superloss_fused(const float* __restrict__ logits,
                const float* __restrict__ targets,
                float* __restrict__ out,
                int n) {
    int tid = threadIdx.x;
    int gtid = blockIdx.x * NTHR + tid;
    int nv = n >> 2;
    int stride = NBLK * NTHR;

    const float4* lp4 = reinterpret_cast<const float4*>(logits);
    const float4* tp4 = reinterpret_cast<const float4*>(targets);

    u64 d_acc_a = bc(0.0f);
    u64 d_acc_b = bc(0.0f);

    // Guardless unroll-2: 4 LDG.128 front-batched (MLP=4), two independent
    // chains into separate accumulators.
    int i = gtid;
    for (; i + stride < nv; i += 2 * stride) {
        float4 pa = __ldcs(lp4 + i);
        float4 ta = __ldcs(tp4 + i);
        float4 pb = __ldcs(lp4 + i + stride);
        float4 tb = __ldcs(tp4 + i + stride);
        superloss_pair(pa.x, pa.y, ta.x, ta.y, d_acc_a);
        superloss_pair(pb.x, pb.y, tb.x, tb.y, d_acc_b);
        superloss_pair(pa.z, pa.w, ta.z, ta.w, d_acc_a);
        superloss_pair(pb.z, pb.w, tb.z, tb.w, d_acc_b);
    }
    if (i < nv) {
        float4 pa = __ldcs(lp4 + i);
        float4 ta = __ldcs(tp4 + i);
        superloss_pair(pa.x, pa.y, ta.x, ta.y, d_acc_a);
        superloss_pair(pa.z, pa.w, ta.z, ta.w, d_acc_b);
    }

    u64 d_acc = f2add(d_acc_a, d_acc_b);
    float acc0, acc1; upk2(acc0, acc1, d_acc);
    int tail_start = nv << 2;
    for (int k = tail_start + gtid; k < n; k += stride)
        acc0 += superloss_scalar(logits[k], targets[k]);

    float acc = acc0 + acc1;

    __shared__ float s[NTHR];
    __shared__ bool is_last;
    s[tid] = acc;
    __syncthreads();
#pragma unroll
    for (int o = NTHR / 2; o > 0; o >>= 1) {
        if (tid < o) s[tid] += s[tid + o];
        __syncthreads();
    }
    if (tid == 0) {
        g_partial[blockIdx.x] = s[0];
        __threadfence();
        unsigned int prev = atomicInc(&g_count, NBLK - 1);
        is_last = (prev == NBLK - 1);
    }
    __syncthreads();

    if (is_last) {
        __threadfence();
        volatile float* gp = g_partial;
        float a = 0.0f;
        for (int j = tid; j < NBLK; j += NTHR) a += gp[j];
        s[tid] = a;
        __syncthreads();
#pragma unroll
        for (int o = NTHR / 2; o > 0; o >>= 1) {
            if (tid < o) s[tid] += s[tid + o];
            __syncthreads();
        }
        if (tid == 0) out[0] = s[0] * (1.0f / 32.0f);
    }
}

extern "C" void kernel_launch(void* const* d_in, const int* in_sizes, int n_in,
                              void* d_out, int out_size) {
    const float* logits  = (const float*)d_in[0];
    const float* targets = (const float*)d_in[1];
    float* out = (float*)d_out;
    int n = in_sizes[0];

    superloss_fused<<<NBLK, NTHR>>>(logits, targets, out, n);
}

// round 15
// speedup vs baseline: 1.0484x; 1.0228x over previous
#include <cuda_runtime.h>
#include <cuda_bf16.h>

#define NBLK 1184   // 148 SMs * 8 resident blocks
#define NTHR 256

__device__ float g_partial[NBLK];
__device__ unsigned int g_count = 0;

typedef unsigned long long u64;

__device__ __forceinline__ float fast_lg2(float x) {
    float r; asm("lg2.approx.f32 %0, %1;" : "=f"(r) : "f"(x)); return r;
}
__device__ __forceinline__ float fast_sqrt(float x) {
    float r; asm("sqrt.approx.f32 %0, %1;" : "=f"(r) : "f"(x)); return r;
}

// ---- packed f32x2 helpers (sm_103) ----
__device__ __forceinline__ u64 pk2(float a, float b) {
    u64 r; asm("mov.b64 %0, {%1, %2};" : "=l"(r) : "f"(a), "f"(b)); return r;
}
__device__ __forceinline__ void upk2(float& a, float& b, u64 v) {
    asm("mov.b64 {%0, %1}, %2;" : "=f"(a), "=f"(b) : "l"(v));
}
__device__ __forceinline__ u64 f2fma(u64 a, u64 b, u64 c) {
    u64 r; asm("fma.rn.f32x2 %0, %1, %2, %3;" : "=l"(r) : "l"(a), "l"(b), "l"(c)); return r;
}
__device__ __forceinline__ u64 f2mul(u64 a, u64 b) {
    u64 r; asm("mul.rn.f32x2 %0, %1, %2;" : "=l"(r) : "l"(a), "l"(b)); return r;
}
__device__ __forceinline__ u64 f2add(u64 a, u64 b) {
    u64 r; asm("add.rn.f32x2 %0, %1, %2;" : "=l"(r) : "l"(a), "l"(b)); return r;
}
__device__ __forceinline__ u64 bc(float x) { return pk2(x, x); }

// q = l1p2 + t*(lp2 - l1p2) = -l/ln2.
//   rho^2  = q*K1 + K2 ; loss_c = q*K3 + K4
// Select on sign of rho^2 — the same value is fed to sqrt, so the NaN lanes
// from sqrt(negative) are exactly the lanes the select discards.
// Init poly pre-scaled by sqrt(0.9): u' = rho*h'(rho); loss_u = u'^2 - 0.9.
__device__ __forceinline__ void superloss_pair(float p0, float p1, float t0, float t1,
                                               u64& d_acc) {
    const u64 C_M1  = bc(-1.0f);
    const u64 C_K1  = bc(-2.0935215460f);
    const u64 C_K2  = bc(-2.5304697141f);
    const u64 C_K3  = bc(-1.8841698127f);
    const u64 C_K4  = bc(-3.1774227427f);
    const u64 C_M09 = bc(-0.9f);
    const u64 C_P6 = bc(2.588513e-5f);
    const u64 C_P5 = bc(-6.109016e-4f);
    const u64 C_P4 = bc(5.983530e-3f);
    const u64 C_P3 = bc(-3.2366116e-2f);
    const u64 C_P2 = bc(0.112574175f);
    const u64 C_P1 = bc(-0.305701133f);
    const u64 C_P0 = bc(0.9486832981f);

    float a0 = fast_lg2(p0),        a1 = fast_lg2(p1);
    float b0 = fast_lg2(1.0f - p0), b1 = fast_lg2(1.0f - p1);

    u64 d_lp  = pk2(a0, a1);
    u64 d_l1p = pk2(b0, b1);
    u64 d_t   = pk2(t0, t1);

    u64 d_diff = f2fma(d_l1p, C_M1, d_lp);        // lp2 - l1p2
    u64 d_q    = f2fma(d_t, d_diff, d_l1p);       // q
    u64 d_r2   = f2fma(d_q, C_K1, C_K2);          // rho^2 (<0 <=> clamped)
    u64 d_lc   = f2fma(d_q, C_K3, C_K4);          // clamped loss

    float r20, r21; upk2(r20, r21, d_r2);
    float s0 = fast_sqrt(r20);                    // NaN if clamped (discarded)
    float s1 = fast_sqrt(r21);
    u64 d_rho = pk2(s0, s1);

    u64 h = f2fma(C_P6, d_rho, C_P5);
    h = f2fma(h, d_rho, C_P4);
    h = f2fma(h, d_rho, C_P3);
    h = f2fma(h, d_rho, C_P2);
    h = f2fma(h, d_rho, C_P1);
    h = f2fma(h, d_rho, C_P0);
    u64 d_u  = f2mul(d_rho, h);                   // u' = sqrt(0.9)*(W+1)
    u64 d_lu = f2fma(d_u, d_u, C_M09);            // loss_u = u'^2 - 0.9

    float lu0, lu1; upk2(lu0, lu1, d_lu);
    float lc0, lc1; upk2(lc0, lc1, d_lc);
    float r0 = (r20 < 0.0f) ? lc0 : lu0;
    float r1 = (r21 < 0.0f) ? lc1 : lu1;
    d_acc = f2add(d_acc, pk2(r0, r1));
}

__device__ __forceinline__ float superloss_scalar(float p, float t) {
    float lp2  = fast_lg2(p);
    float l1p2 = fast_lg2(1.0f - p);
    float q = fmaf(t, lp2 - l1p2, l1p2);
    float r2 = fmaf(q, -2.0935215460f, -2.5304697141f);
    float lc = fmaf(q, -1.8841698127f, -3.1774227427f);
    float rho = fast_sqrt(r2);
    float h = fmaf(rho, 2.588513e-5f, -6.109016e-4f);
    h = fmaf(h, rho,  5.983530e-3f);
    h = fmaf(h, rho, -3.2366116e-2f);
    h = fmaf(h, rho,  0.112574175f);
    h = fmaf(h, rho, -0.305701133f);
    h = fmaf(h, rho,  0.9486832981f);
    float u = rho * h;
    float lu = fmaf(u, u, -0.9f);
    return (r2 < 0.0f) ? lc : lu;
}

__global__ void __launch_bounds__(NTHR, 8)
superloss_fused(const float* __restrict__ logits,
                const float* __restrict__ targets,
                float* __restrict__ out,
                int n) {
    int tid = threadIdx.x;
    int gtid = blockIdx.x * NTHR + tid;
    int nv = n >> 2;
    int stride = NBLK * NTHR;

    const float4* lp4 = reinterpret_cast<const float4*>(logits);
    const float4* tp4 = reinterpret_cast<const float4*>(targets);

    u64 d_acc = bc(0.0f);
    for (int i = gtid; i < nv; i += stride) {
        float4 p4 = __ldcs(lp4 + i);
        float4 t4 = __ldcs(tp4 + i);
        superloss_pair(p4.x, p4.y, t4.x, t4.y, d_acc);
        superloss_pair(p4.z, p4.w, t4.z, t4.w, d_acc);
    }
    float acc0, acc1; upk2(acc0, acc1, d_acc);
    int tail_start = nv << 2;
    for (int k = tail_start + gtid; k < n; k += stride)
        acc0 += superloss_scalar(logits[k], targets[k]);

    float acc = acc0 + acc1;

    __shared__ float s[NTHR];
    __shared__ bool is_last;
    s[tid] = acc;
    __syncthreads();
#pragma unroll
    for (int o = NTHR / 2; o > 0; o >>= 1) {
        if (tid < o) s[tid] += s[tid + o];
        __syncthreads();
    }
    if (tid == 0) {
        g_partial[blockIdx.x] = s[0];
        __threadfence();
        unsigned int prev = atomicInc(&g_count, NBLK - 1);
        is_last = (prev == NBLK - 1);
    }
    __syncthreads();

    if (is_last) {
        __threadfence();
        volatile float* gp = g_partial;
        float a = 0.0f;
        for (int j = tid; j < NBLK; j += NTHR) a += gp[j];
        s[tid] = a;
        __syncthreads();
#pragma unroll
        for (int o = NTHR / 2; o > 0; o >>= 1) {
            if (tid < o) s[tid] += s[tid + o];
            __syncthreads();
        }
        if (tid == 0) out[0] = s[0] * (1.0f / 32.0f);
    }
}

extern "C" void kernel_launch(void* const* d_in, const int* in_sizes, int n_in,
                              void* d_out, int out_size) {
    const float* logits  = (const float*)d_in[0];
    const float* targets = (const float*)d_in[1];
    float* out = (float*)d_out;
    int n = in_sizes[0];

    superloss_fused<<<NBLK, NTHR>>>(logits, targets, out, n);
}

// round 16
// speedup vs baseline: 1.0901x; 1.0398x over previous
#include <cuda_runtime.h>
#include <cuda_bf16.h>

#define NBLK 1184   // 148 SMs * 8 resident blocks
#define NTHR 256

__device__ float g_partial[NBLK];
__device__ unsigned int g_count = 0;

typedef unsigned long long u64;

__device__ __forceinline__ float fast_lg2(float x) {
    float r; asm("lg2.approx.f32 %0, %1;" : "=f"(r) : "f"(x)); return r;
}
__device__ __forceinline__ float fast_sqrt(float x) {
    float r; asm("sqrt.approx.f32 %0, %1;" : "=f"(r) : "f"(x)); return r;
}
__device__ __forceinline__ void prefetch_l2(const void* p) {
    asm volatile("prefetch.global.L2 [%0];" :: "l"(p));
}

// ---- packed f32x2 helpers (sm_103) ----
__device__ __forceinline__ u64 pk2(float a, float b) {
    u64 r; asm("mov.b64 %0, {%1, %2};" : "=l"(r) : "f"(a), "f"(b)); return r;
}
__device__ __forceinline__ void upk2(float& a, float& b, u64 v) {
    asm("mov.b64 {%0, %1}, %2;" : "=f"(a), "=f"(b) : "l"(v));
}
__device__ __forceinline__ u64 f2fma(u64 a, u64 b, u64 c) {
    u64 r; asm("fma.rn.f32x2 %0, %1, %2, %3;" : "=l"(r) : "l"(a), "l"(b), "l"(c)); return r;
}
__device__ __forceinline__ u64 f2mul(u64 a, u64 b) {
    u64 r; asm("mul.rn.f32x2 %0, %1, %2;" : "=l"(r) : "l"(a), "l"(b)); return r;
}
__device__ __forceinline__ u64 f2add(u64 a, u64 b) {
    u64 r; asm("add.rn.f32x2 %0, %1, %2;" : "=l"(r) : "l"(a), "l"(b)); return r;
}
__device__ __forceinline__ u64 bc(float x) { return pk2(x, x); }

// q = l1p2 + t*(lp2 - l1p2) = -l/ln2.
//   rho^2  = q*K1 + K2 ; loss_c = q*K3 + K4
// Select on sign of rho^2 — the same value is fed to sqrt, so the NaN lanes
// from sqrt(negative) are exactly the lanes the select discards.
// Init poly pre-scaled by sqrt(0.9): u' = rho*h'(rho); loss_u = u'^2 - 0.9.
__device__ __forceinline__ void superloss_pair(float p0, float p1, float t0, float t1,
                                               u64& d_acc) {
    const u64 C_M1  = bc(-1.0f);
    const u64 C_K1  = bc(-2.0935215460f);
    const u64 C_K2  = bc(-2.5304697141f);
    const u64 C_K3  = bc(-1.8841698127f);
    const u64 C_K4  = bc(-3.1774227427f);
    const u64 C_M09 = bc(-0.9f);
    const u64 C_P6 = bc(2.588513e-5f);
    const u64 C_P5 = bc(-6.109016e-4f);
    const u64 C_P4 = bc(5.983530e-3f);
    const u64 C_P3 = bc(-3.2366116e-2f);
    const u64 C_P2 = bc(0.112574175f);
    const u64 C_P1 = bc(-0.305701133f);
    const u64 C_P0 = bc(0.9486832981f);

    float a0 = fast_lg2(p0),        a1 = fast_lg2(p1);
    float b0 = fast_lg2(1.0f - p0), b1 = fast_lg2(1.0f - p1);

    u64 d_lp  = pk2(a0, a1);
    u64 d_l1p = pk2(b0, b1);
    u64 d_t   = pk2(t0, t1);

    u64 d_diff = f2fma(d_l1p, C_M1, d_lp);        // lp2 - l1p2
    u64 d_q    = f2fma(d_t, d_diff, d_l1p);       // q
    u64 d_r2   = f2fma(d_q, C_K1, C_K2);          // rho^2 (<0 <=> clamped)
    u64 d_lc   = f2fma(d_q, C_K3, C_K4);          // clamped loss

    float r20, r21; upk2(r20, r21, d_r2);
    float s0 = fast_sqrt(r20);                    // NaN if clamped (discarded)
    float s1 = fast_sqrt(r21);
    u64 d_rho = pk2(s0, s1);

    u64 h = f2fma(C_P6, d_rho, C_P5);
    h = f2fma(h, d_rho, C_P4);
    h = f2fma(h, d_rho, C_P3);
    h = f2fma(h, d_rho, C_P2);
    h = f2fma(h, d_rho, C_P1);
    h = f2fma(h, d_rho, C_P0);
    u64 d_u  = f2mul(d_rho, h);                   // u' = sqrt(0.9)*(W+1)
    u64 d_lu = f2fma(d_u, d_u, C_M09);            // loss_u = u'^2 - 0.9

    float lu0, lu1; upk2(lu0, lu1, d_lu);
    float lc0, lc1; upk2(lc0, lc1, d_lc);
    float r0 = (r20 < 0.0f) ? lc0 : lu0;
    float r1 = (r21 < 0.0f) ? lc1 : lu1;
    d_acc = f2add(d_acc, pk2(r0, r1));
}

__device__ __forceinline__ float superloss_scalar(float p, float t) {
    float lp2  = fast_lg2(p);
    float l1p2 = fast_lg2(1.0f - p);
    float q = fmaf(t, lp2 - l1p2, l1p2);
    float r2 = fmaf(q, -2.0935215460f, -2.5304697141f);
    float lc = fmaf(q, -1.8841698127f, -3.1774227427f);
    float rho = fast_sqrt(r2);
    float h = fmaf(rho, 2.588513e-5f, -6.109016e-4f);
    h = fmaf(h, rho,  5.983530e-3f);
    h = fmaf(h, rho, -3.2366116e-2f);
    h = fmaf(h, rho,  0.112574175f);
    h = fmaf(h, rho, -0.305701133f);
    h = fmaf(h, rho,  0.9486832981f);
    float u = rho * h;
    float lu = fmaf(u, u, -0.9f);
    return (r2 < 0.0f) ? lc : lu;
}

__global__ void __launch_bounds__(NTHR, 8)
superloss_fused(const float* __restrict__ logits,
                const float* __restrict__ targets,
                float* __restrict__ out,
                int n) {
    int tid = threadIdx.x;
    int gtid = blockIdx.x * NTHR + tid;
    int nv = n >> 2;
    int stride = NBLK * NTHR;

    const float4* lp4 = reinterpret_cast<const float4*>(logits);
    const float4* tp4 = reinterpret_cast<const float4*>(targets);

    u64 d_acc = bc(0.0f);
    for (int i = gtid; i < nv; i += stride) {
        // register-free latency hiding: pull iteration i+stride's lines into
        // L2 while computing iteration i (clamped to stay in-bounds).
        int ip = i + stride;
        ip = (ip < nv) ? ip : i;
        prefetch_l2(lp4 + ip);
        prefetch_l2(tp4 + ip);

        float4 p4 = __ldcs(lp4 + i);
        float4 t4 = __ldcs(tp4 + i);
        superloss_pair(p4.x, p4.y, t4.x, t4.y, d_acc);
        superloss_pair(p4.z, p4.w, t4.z, t4.w, d_acc);
    }
    float acc0, acc1; upk2(acc0, acc1, d_acc);
    int tail_start = nv << 2;
    for (int k = tail_start + gtid; k < n; k += stride)
        acc0 += superloss_scalar(logits[k], targets[k]);

    float acc = acc0 + acc1;

    __shared__ float s[NTHR];
    __shared__ bool is_last;
    s[tid] = acc;
    __syncthreads();
#pragma unroll
    for (int o = NTHR / 2; o > 0; o >>= 1) {
        if (tid < o) s[tid] += s[tid + o];
        __syncthreads();
    }
    if (tid == 0) {
        g_partial[blockIdx.x] = s[0];
        __threadfence();
        unsigned int prev = atomicInc(&g_count, NBLK - 1);
        is_last = (prev == NBLK - 1);
    }
    __syncthreads();

    if (is_last) {
        __threadfence();
        volatile float* gp = g_partial;
        float a = 0.0f;
        for (int j = tid; j < NBLK; j += NTHR) a += gp[j];
        s[tid] = a;
        __syncthreads();
#pragma unroll
        for (int o = NTHR / 2; o > 0; o >>= 1) {
            if (tid < o) s[tid] += s[tid + o];
            __syncthreads();
        }
        if (tid == 0) out[0] = s[0] * (1.0f / 32.0f);
    }
}

extern "C" void kernel_launch(void* const* d_in, const int* in_sizes, int n_in,
                              void* d_out, int out_size) {
    const float* logits  = (const float*)d_in[0];
    const float* targets = (const float*)d_in[1];
    float* out = (float*)d_out;
    int n = in_sizes[0];

    superloss_fused<<<NBLK, NTHR>>>(logits, targets, out, n);
}

// round 17
// speedup vs baseline: 1.0955x; 1.0049x over previous
#include <cuda_runtime.h>
#include <cuda_bf16.h>

#define NBLK 1184   // 148 SMs * 8 resident blocks
#define NTHR 256

__device__ float g_partial[NBLK];
__device__ unsigned int g_count = 0;

typedef unsigned long long u64;

__device__ __forceinline__ float fast_lg2(float x) {
    float r; asm("lg2.approx.f32 %0, %1;" : "=f"(r) : "f"(x)); return r;
}
__device__ __forceinline__ float fast_sqrt(float x) {
    float r; asm("sqrt.approx.f32 %0, %1;" : "=f"(r) : "f"(x)); return r;
}
// Predicated L2 prefetch: issues only when pred != 0 (predicated-off memory
// ops do not dispatch to the LSU).
__device__ __forceinline__ void prefetch_l2_pred(const void* p, unsigned pred) {
    asm volatile(
        "{\n\t"
        ".reg .pred q;\n\t"
        "setp.ne.u32 q, %1, 0;\n\t"
        "@q prefetch.global.L2 [%0];\n\t"
        "}" :: "l"(p), "r"(pred));
}

// ---- packed f32x2 helpers (sm_103) ----
__device__ __forceinline__ u64 pk2(float a, float b) {
    u64 r; asm("mov.b64 %0, {%1, %2};" : "=l"(r) : "f"(a), "f"(b)); return r;
}
__device__ __forceinline__ void upk2(float& a, float& b, u64 v) {
    asm("mov.b64 {%0, %1}, %2;" : "=f"(a), "=f"(b) : "l"(v));
}
__device__ __forceinline__ u64 f2fma(u64 a, u64 b, u64 c) {
    u64 r; asm("fma.rn.f32x2 %0, %1, %2, %3;" : "=l"(r) : "l"(a), "l"(b), "l"(c)); return r;
}
__device__ __forceinline__ u64 f2mul(u64 a, u64 b) {
    u64 r; asm("mul.rn.f32x2 %0, %1, %2;" : "=l"(r) : "l"(a), "l"(b)); return r;
}
__device__ __forceinline__ u64 f2add(u64 a, u64 b) {
    u64 r; asm("add.rn.f32x2 %0, %1, %2;" : "=l"(r) : "l"(a), "l"(b)); return r;
}
__device__ __forceinline__ u64 bc(float x) { return pk2(x, x); }

// q = l1p2 + t*(lp2 - l1p2) = -l/ln2.
//   rho^2  = q*K1 + K2 ; loss_c = q*K3 + K4
// Select on sign of rho^2 — the same value is fed to sqrt, so the NaN lanes
// from sqrt(negative) are exactly the lanes the select discards.
// Init poly pre-scaled by sqrt(0.9): u' = rho*h'(rho); loss_u = u'^2 - 0.9.
__device__ __forceinline__ void superloss_pair(float p0, float p1, float t0, float t1,
                                               u64& d_acc) {
    const u64 C_M1  = bc(-1.0f);
    const u64 C_K1  = bc(-2.0935215460f);
    const u64 C_K2  = bc(-2.5304697141f);
    const u64 C_K3  = bc(-1.8841698127f);
    const u64 C_K4  = bc(-3.1774227427f);
    const u64 C_M09 = bc(-0.9f);
    const u64 C_P6 = bc(2.588513e-5f);
    const u64 C_P5 = bc(-6.109016e-4f);
    const u64 C_P4 = bc(5.983530e-3f);
    const u64 C_P3 = bc(-3.2366116e-2f);
    const u64 C_P2 = bc(0.112574175f);
    const u64 C_P1 = bc(-0.305701133f);
    const u64 C_P0 = bc(0.9486832981f);

    float a0 = fast_lg2(p0),        a1 = fast_lg2(p1);
    float b0 = fast_lg2(1.0f - p0), b1 = fast_lg2(1.0f - p1);

    u64 d_lp  = pk2(a0, a1);
    u64 d_l1p = pk2(b0, b1);
    u64 d_t   = pk2(t0, t1);

    u64 d_diff = f2fma(d_l1p, C_M1, d_lp);        // lp2 - l1p2
    u64 d_q    = f2fma(d_t, d_diff, d_l1p);       // q
    u64 d_r2   = f2fma(d_q, C_K1, C_K2);          // rho^2 (<0 <=> clamped)
    u64 d_lc   = f2fma(d_q, C_K3, C_K4);          // clamped loss

    float r20, r21; upk2(r20, r21, d_r2);
    float s0 = fast_sqrt(r20);                    // NaN if clamped (discarded)
    float s1 = fast_sqrt(r21);
    u64 d_rho = pk2(s0, s1);

    u64 h = f2fma(C_P6, d_rho, C_P5);
    h = f2fma(h, d_rho, C_P4);
    h = f2fma(h, d_rho, C_P3);
    h = f2fma(h, d_rho, C_P2);
    h = f2fma(h, d_rho, C_P1);
    h = f2fma(h, d_rho, C_P0);
    u64 d_u  = f2mul(d_rho, h);                   // u' = sqrt(0.9)*(W+1)
    u64 d_lu = f2fma(d_u, d_u, C_M09);            // loss_u = u'^2 - 0.9

    float lu0, lu1; upk2(lu0, lu1, d_lu);
    float lc0, lc1; upk2(lc0, lc1, d_lc);
    float r0 = (r20 < 0.0f) ? lc0 : lu0;
    float r1 = (r21 < 0.0f) ? lc1 : lu1;
    d_acc = f2add(d_acc, pk2(r0, r1));
}

__device__ __forceinline__ float superloss_scalar(float p, float t) {
    float lp2  = fast_lg2(p);
    float l1p2 = fast_lg2(1.0f - p);
    float q = fmaf(t, lp2 - l1p2, l1p2);
    float r2 = fmaf(q, -2.0935215460f, -2.5304697141f);
    float lc = fmaf(q, -1.8841698127f, -3.1774227427f);
    float rho = fast_sqrt(r2);
    float h = fmaf(rho, 2.588513e-5f, -6.109016e-4f);
    h = fmaf(h, rho,  5.983530e-3f);
    h = fmaf(h, rho, -3.2366116e-2f);
    h = fmaf(h, rho,  0.112574175f);
    h = fmaf(h, rho, -0.305701133f);
    h = fmaf(h, rho,  0.9486832981f);
    float u = rho * h;
    float lu = fmaf(u, u, -0.9f);
    return (r2 < 0.0f) ? lc : lu;
}

__global__ void __launch_bounds__(NTHR, 8)
superloss_fused(const float* __restrict__ logits,
                const float* __restrict__ targets,
                float* __restrict__ out,
                int n) {
    int tid = threadIdx.x;
    int gtid = blockIdx.x * NTHR + tid;
    int nv = n >> 2;
    int stride = NBLK * NTHR;

    const float4* lp4 = reinterpret_cast<const float4*>(logits);
    const float4* tp4 = reinterpret_cast<const float4*>(targets);

    // One prefetch per 128B line: lanes 0,8,16,24 cover the warp's 512B.
    unsigned pf_lane = ((tid & 7) == 0) ? 1u : 0u;

    u64 d_acc = bc(0.0f);
    for (int i = gtid; i < nv; i += stride) {
        // register-free latency hiding: pull iteration i+stride's lines into
        // L2 while computing iteration i (clamped to stay in-bounds).
        int ip = i + stride;
        ip = (ip < nv) ? ip : i;
        prefetch_l2_pred(lp4 + ip, pf_lane);
        prefetch_l2_pred(tp4 + ip, pf_lane);

        float4 p4 = __ldcs(lp4 + i);
        float4 t4 = __ldcs(tp4 + i);
        superloss_pair(p4.x, p4.y, t4.x, t4.y, d_acc);
        superloss_pair(p4.z, p4.w, t4.z, t4.w, d_acc);
    }
    float acc0, acc1; upk2(acc0, acc1, d_acc);
    int tail_start = nv << 2;
    for (int k = tail_start + gtid; k < n; k += stride)
        acc0 += superloss_scalar(logits[k], targets[k]);

    float acc = acc0 + acc1;

    __shared__ float s[NTHR];
    __shared__ bool is_last;
    s[tid] = acc;
    __syncthreads();
#pragma unroll
    for (int o = NTHR / 2; o > 0; o >>= 1) {
        if (tid < o) s[tid] += s[tid + o];
        __syncthreads();
    }
    if (tid == 0) {
        g_partial[blockIdx.x] = s[0];
        __threadfence();
        unsigned int prev = atomicInc(&g_count, NBLK - 1);
        is_last = (prev == NBLK - 1);
    }
    __syncthreads();

    if (is_last) {
        __threadfence();
        volatile float* gp = g_partial;
        float a = 0.0f;
        for (int j = tid; j < NBLK; j += NTHR) a += gp[j];
        s[tid] = a;
        __syncthreads();
#pragma unroll
        for (int o = NTHR / 2; o > 0; o >>= 1) {
            if (tid < o) s[tid] += s[tid + o];
            __syncthreads();
        }
        if (tid == 0) out[0] = s[0] * (1.0f / 32.0f);
    }
}

extern "C" void kernel_launch(void* const* d_in, const int* in_sizes, int n_in,
                              void* d_out, int out_size) {
    const float* logits  = (const float*)d_in[0];
    const float* targets = (const float*)d_in[1];
    float* out = (float*)d_out;
    int n = in_sizes[0];

    superloss_fused<<<NBLK, NTHR>>>(logits, targets, out, n);
}